// round 2
// baseline (speedup 1.0000x reference)
#include <cuda_runtime.h>
#include <math.h>

#define B_ 4
#define C_ 128
#define H_ 128
#define W_ 128
#define O_ 256
#define K2_ 9
#define OFFC 27
#define HW_ (H_*W_)
#define NPX (B_*HW_)

// ---------------- scratch (device globals: no allocation allowed) ----------------
__device__ float g_xnhwc[B_*HW_*C_];     // [b][h][w][c]   33.5 MB
__device__ float g_offmask[NPX*OFFC];    // [b][h][w][27]  (masks pre-sigmoided)
__device__ float g_mid[NPX*C_];          // [b][h][w][c]   33.5 MB

// ---------------- kernel 1: NCHW -> NHWC transpose ----------------
__global__ void k_transpose(const float* __restrict__ x) {
    __shared__ float tile[32][33];
    const int b  = blockIdx.z;
    const int c0 = blockIdx.y * 32;
    const int p0 = blockIdx.x * 32;
    const int tx = threadIdx.x, ty = threadIdx.y;   // (32, 8)
    const float* xb = x + (size_t)b * C_ * HW_;
    #pragma unroll
    for (int j = 0; j < 32; j += 8)
        tile[ty + j][tx] = xb[(size_t)(c0 + ty + j) * HW_ + p0 + tx];
    __syncthreads();
    float* xnb = g_xnhwc + (size_t)b * HW_ * C_;
    #pragma unroll
    for (int j = 0; j < 32; j += 8)
        xnb[(size_t)(p0 + ty + j) * C_ + c0 + tx] = tile[tx][ty + j];
}

// ---------------- kernel 2: offset conv (27 x 1152 implicit GEMM) ----------------
// Block: 128 threads = columns, tile = 2 rows (h0, h0+1) of full width.
// Channel chunks of 32. x tile in smem [4 rows][32 c][133 pitch], weights in smem.
#define XS_PITCH 133
#define XS_ELEMS (4*32*XS_PITCH)
#define WS_ELEMS (OFFC*288)
#define SMEM_B_BYTES ((XS_ELEMS + WS_ELEMS)*4)

__global__ void k_offconv(const float* __restrict__ wof, const float* __restrict__ bof) {
    extern __shared__ float sm[];
    float* xs = sm;                 // [r][c][col] pitch 133, cols -1..128 at idx 0..129
    float* ws = sm + XS_ELEMS;      // ws[o*288 + c*9 + tap]
    const int b  = blockIdx.y;
    const int h0 = blockIdx.x * 2;
    const int t  = threadIdx.x;     // column 0..127

    float acc0[OFFC], acc1[OFFC];
    #pragma unroll
    for (int o = 0; o < OFFC; o++) { acc0[o] = 0.f; acc1[o] = 0.f; }

    for (int cc = 0; cc < 4; cc++) {
        // load x tile (rows h0-1..h0+2, cols -1..128, channels cc*32..+31), zero-padded
        for (int i = t; i < 4 * 130 * 32; i += 128) {
            int c   = i & 31;
            int col = (i >> 5) % 130;
            int r   = i / (130 * 32);
            int grow = h0 - 1 + r, gcol = col - 1;
            float v = 0.f;
            if (grow >= 0 && grow < H_ && gcol >= 0 && gcol < W_)
                v = g_xnhwc[((b * H_ + grow) * W_ + gcol) * C_ + cc * 32 + c];
            xs[(r * 32 + c) * XS_PITCH + col] = v;
        }
        // load weight chunk
        for (int i = t; i < WS_ELEMS; i += 128) {
            int o = i / 288, rem = i - o * 288;
            ws[i] = wof[o * 1152 + cc * 288 + rem];
        }
        __syncthreads();

        for (int cl = 0; cl < 32; cl++) {
            float xv[4][3];
            #pragma unroll
            for (int r = 0; r < 4; r++)
                #pragma unroll
                for (int j = 0; j < 3; j++)
                    xv[r][j] = xs[(r * 32 + cl) * XS_PITCH + t + j];
            #pragma unroll
            for (int tap = 0; tap < 9; tap++) {
                const int ky = tap / 3, kx = tap % 3;
                const float* wp = ws + cl * 9 + tap;
                #pragma unroll
                for (int o = 0; o < OFFC; o++) {
                    float wv = wp[o * 288];           // broadcast LDS
                    acc0[o] = fmaf(wv, xv[ky][kx],     acc0[o]);
                    acc1[o] = fmaf(wv, xv[ky + 1][kx], acc1[o]);
                }
            }
        }
        __syncthreads();
    }

    #pragma unroll
    for (int o = 0; o < OFFC; o++) {
        float v0 = acc0[o] + bof[o];
        float v1 = acc1[o] + bof[o];
        if (o >= 18) {
            v0 = 1.f / (1.f + expf(-v0));
            v1 = 1.f / (1.f + expf(-v1));
        }
        g_offmask[((b * H_ + h0    ) * W_ + t) * OFFC + o] = v0;
        g_offmask[((b * H_ + h0 + 1) * W_ + t) * OFFC + o] = v1;
    }
}

// ---------------- kernel 3: deform bilinear sample + depthwise ----------------
// Block = one pixel, 128 threads = channels. Validity+mask folded into corner weights.
__global__ void k_deform(const float* __restrict__ wdw, const float* __restrict__ bdw) {
    const int w = blockIdx.x, h = blockIdx.y, b = blockIdx.z;
    const int c = threadIdx.x;
    __shared__ int   s_idx[9][4];
    __shared__ float s_wt [9][4];
    if (c < 9) {
        const int k = c;
        const int base = ((b * H_ + h) * W_ + w) * OFFC;
        float dy = g_offmask[base + 2 * k];
        float dx = g_offmask[base + 2 * k + 1];
        float mk = g_offmask[base + 18 + k];      // already sigmoided
        float py = (float)h + (float)(k / 3 - 1) + dy;
        float px = (float)w + (float)(k % 3 - 1) + dx;
        float y0f = floorf(py), x0f = floorf(px);
        float wy = py - y0f, wx = px - x0f;
        int y0 = (int)y0f, x0 = (int)x0f;
        #pragma unroll
        for (int cor = 0; cor < 4; cor++) {
            int iy = cor >> 1, ix = cor & 1;
            int yc = y0 + iy, xc = x0 + ix;
            float valid = (yc >= 0 && yc < H_ && xc >= 0 && xc < W_) ? 1.f : 0.f;
            int yi = min(max(yc, 0), H_ - 1);
            int xi = min(max(xc, 0), W_ - 1);
            s_idx[k][cor] = ((b * H_ + yi) * W_ + xi) * C_;
            s_wt [k][cor] = valid * mk * (iy ? wy : 1.f - wy) * (ix ? wx : 1.f - wx);
        }
    }
    __syncthreads();
    float acc = bdw[c];
    #pragma unroll
    for (int k = 0; k < 9; k++) {
        float v = s_wt[k][0] * g_xnhwc[s_idx[k][0] + c]
                + s_wt[k][1] * g_xnhwc[s_idx[k][1] + c]
                + s_wt[k][2] * g_xnhwc[s_idx[k][2] + c]
                + s_wt[k][3] * g_xnhwc[s_idx[k][3] + c];
        acc = fmaf(v, wdw[c * 9 + k], acc);
    }
    g_mid[((b * H_ + h) * W_ + w) * C_ + c] = acc;
}

// ---------------- kernel 4: pointwise 256x128 GEMM over 65536 pixels ----------------
// Tile 128 px x 128 o, K=128 in one slab; 256 threads, 8x8 register tile each.
#define PW_PITCH 129
#define SMEM_D_BYTES (2*128*PW_PITCH*4)

__global__ void k_pointwise(const float* __restrict__ wpw, const float* __restrict__ bpw,
                            float* __restrict__ out) {
    extern __shared__ float sm[];
    float* sx = sm;                  // sx[c*129 + px]
    float* sw = sm + 128 * PW_PITCH; // sw[c*129 + o]
    const int tid = threadIdx.x;
    const int p0  = blockIdx.x * 128;
    const int ot  = blockIdx.y * 128;

    for (int i = tid; i < 16384; i += 256) {
        int c = i & 127, px = i >> 7;
        sx[c * PW_PITCH + px] = g_mid[(p0 + px) * C_ + c];
    }
    for (int i = tid; i < 16384; i += 256) {
        int c = i & 127, o = i >> 7;
        sw[c * PW_PITCH + o] = wpw[(ot + o) * C_ + c];
    }
    __syncthreads();

    const int pg = tid & 15, og = tid >> 4;
    const int px0 = pg * 8, o0 = og * 8;
    float acc[8][8];
    #pragma unroll
    for (int i = 0; i < 8; i++)
        #pragma unroll
        for (int j = 0; j < 8; j++) acc[i][j] = 0.f;

    #pragma unroll 4
    for (int c = 0; c < 128; c++) {
        float xr[8], wr[8];
        #pragma unroll
        for (int j = 0; j < 8; j++) xr[j] = sx[c * PW_PITCH + px0 + j];
        #pragma unroll
        for (int i = 0; i < 8; i++) wr[i] = sw[c * PW_PITCH + o0 + i];
        #pragma unroll
        for (int i = 0; i < 8; i++)
            #pragma unroll
            for (int j = 0; j < 8; j++)
                acc[i][j] = fmaf(wr[i], xr[j], acc[i][j]);
    }

    const int bb  = p0 >> 14;          // pixel tile lies within one batch image
    const int hw0 = p0 & 16383;
    #pragma unroll
    for (int i = 0; i < 8; i++) {
        const int o = ot + o0 + i;
        const float bias = bpw[o];
        float* op = out + ((size_t)bb * O_ + o) * HW_ + hw0 + px0;
        #pragma unroll
        for (int j = 0; j < 8; j++) op[j] = acc[i][j] + bias;
    }
}

// ---------------- launch ----------------
extern "C" void kernel_launch(void* const* d_in, const int* in_sizes, int n_in,
                              void* d_out, int out_size) {
    const float* x     = (const float*)d_in[0];
    const float* w_off = (const float*)d_in[1];
    const float* b_off = (const float*)d_in[2];
    const float* w_dw  = (const float*)d_in[3];
    const float* b_dw  = (const float*)d_in[4];
    const float* w_pw  = (const float*)d_in[5];
    const float* b_pw  = (const float*)d_in[6];
    float* out = (float*)d_out;

    cudaFuncSetAttribute(k_offconv,   cudaFuncAttributeMaxDynamicSharedMemorySize, SMEM_B_BYTES);
    cudaFuncSetAttribute(k_pointwise, cudaFuncAttributeMaxDynamicSharedMemorySize, SMEM_D_BYTES);

    k_transpose<<<dim3(HW_/32, C_/32, B_), dim3(32, 8)>>>(x);
    k_offconv  <<<dim3(H_/2, B_), 128, SMEM_B_BYTES>>>(w_off, b_off);
    k_deform   <<<dim3(W_, H_, B_), 128>>>(w_dw, b_dw);
    k_pointwise<<<dim3(NPX/128, O_/128), 256, SMEM_D_BYTES>>>(w_pw, b_pw, out);
}

// round 5
// speedup vs baseline: 1.3207x; 1.3207x over previous
#include <cuda_runtime.h>
#include <math.h>

#define B_ 4
#define C_ 128
#define H_ 128
#define W_ 128
#define O_ 256
#define OFFC 27
#define HW_ (H_*W_)
#define NPX (B_*HW_)

// ---------------- scratch (device globals: no allocation allowed) ----------------
__device__ float g_xnhwc[B_*HW_*C_];     // [b][h][w][c]
__device__ float g_offmask[NPX*OFFC];    // [b][h][w][27]  (masks pre-sigmoided)
__device__ float g_mid[NPX*C_];          // [b][h][w][c]

// ---------------- kernel 1: NCHW -> NHWC transpose ----------------
__global__ void k_transpose(const float* __restrict__ x) {
    __shared__ float tile[32][33];
    const int b  = blockIdx.z;
    const int c0 = blockIdx.y * 32;
    const int p0 = blockIdx.x * 32;
    const int tx = threadIdx.x, ty = threadIdx.y;   // (32, 8)
    const float* xb = x + (size_t)b * C_ * HW_;
    #pragma unroll
    for (int j = 0; j < 32; j += 8)
        tile[ty + j][tx] = xb[(size_t)(c0 + ty + j) * HW_ + p0 + tx];
    __syncthreads();
    float* xnb = g_xnhwc + (size_t)b * HW_ * C_;
    #pragma unroll
    for (int j = 0; j < 32; j += 8)
        xnb[(size_t)(p0 + ty + j) * C_ + c0 + tx] = tile[tx][ty + j];
}

// ---------------- kernel 2: offset conv (27 x 1152 implicit GEMM) ----------------
// 256 threads = 128 cols x 2 channel-groups (64 ch each). Tile = 2 output rows.
// Per chunk: 16 channels per group in smem. Cross-group reduction through smem.
#define XP2 133
#define XS2_ELEMS (2*4*16*XP2)      // 17024 floats
#define WS2_ELEMS (2*27*16*9)       // 7776 floats
#define OFF_SMEM ((XS2_ELEMS + WS2_ELEMS)*4)

__global__ void k_offconv(const float* __restrict__ wof, const float* __restrict__ bof) {
    extern __shared__ float sm[];
    float* xs = sm;                  // xs[((g*4+r)*16+c)*XP2 + col]   cols -1..128 at 0..129
    float* ws = sm + XS2_ELEMS;      // ws[((g*27+o)*16+c)*9 + tap]
    const int b  = blockIdx.y;
    const int h0 = blockIdx.x * 2;
    const int t  = threadIdx.x;      // 0..255
    const int col = t & 127;
    const int g   = t >> 7;          // channel group

    float acc0[OFFC], acc1[OFFC];
    #pragma unroll
    for (int o = 0; o < OFFC; o++) { acc0[o] = 0.f; acc1[o] = 0.f; }

    for (int cc = 0; cc < 4; cc++) {
        // x tile: 2 groups x 4 rows x 16 ch x 130 cols
        for (int i = t; i < 2*4*16*130; i += 256) {
            int c = i & 15;
            int j = i >> 4;
            int colx = j % 130; j /= 130;
            int r  = j & 3;
            int gg = j >> 2;
            int grow = h0 - 1 + r, gcol = colx - 1;
            float v = 0.f;
            if (grow >= 0 && grow < H_ && gcol >= 0 && gcol < W_)
                v = g_xnhwc[((b * H_ + grow) * W_ + gcol) * C_ + gg * 64 + cc * 16 + c];
            xs[((gg * 4 + r) * 16 + c) * XP2 + colx] = v;
        }
        // weights: 2 groups x 27 o x 16 ch x 9 taps
        for (int i = t; i < WS2_ELEMS; i += 256) {
            int gg = i / 3888;
            int rem = i - gg * 3888;
            int o = rem / 144;
            int rem2 = rem - o * 144;
            int c = rem2 / 9;
            int tap = rem2 - c * 9;
            ws[i] = wof[o * 1152 + (gg * 64 + cc * 16 + c) * 9 + tap];
        }
        __syncthreads();

        for (int cl = 0; cl < 16; cl++) {
            float xv[4][3];
            #pragma unroll
            for (int r = 0; r < 4; r++)
                #pragma unroll
                for (int j = 0; j < 3; j++)
                    xv[r][j] = xs[((g * 4 + r) * 16 + cl) * XP2 + col + j];
            #pragma unroll
            for (int tap = 0; tap < 9; tap++) {
                const int ky = tap / 3, kx = tap % 3;
                const float* wp = ws + (g * 27 * 16 + cl) * 9 + tap;
                #pragma unroll
                for (int o = 0; o < OFFC; o++) {
                    float wv = wp[o * 144];           // uniform -> broadcast LDS
                    acc0[o] = fmaf(wv, xv[ky][kx],     acc0[o]);
                    acc1[o] = fmaf(wv, xv[ky + 1][kx], acc1[o]);
                }
            }
        }
        __syncthreads();
    }

    // cross-group reduction through smem (reuse xs region)
    float* red = sm;   // 128 cols * 54 floats
    if (g == 1) {
        #pragma unroll
        for (int o = 0; o < OFFC; o++) {
            red[col * 54 + o]        = acc0[o];
            red[col * 54 + 27 + o]   = acc1[o];
        }
    }
    __syncthreads();
    if (g == 0) {
        #pragma unroll
        for (int o = 0; o < OFFC; o++) {
            float v0 = acc0[o] + red[col * 54 + o]      + bof[o];
            float v1 = acc1[o] + red[col * 54 + 27 + o] + bof[o];
            if (o >= 18) {
                v0 = 1.f / (1.f + expf(-v0));
                v1 = 1.f / (1.f + expf(-v1));
            }
            g_offmask[((b * H_ + h0    ) * W_ + col) * OFFC + o] = v0;
            g_offmask[((b * H_ + h0 + 1) * W_ + col) * OFFC + o] = v1;
        }
    }
}

// ---------------- kernel 3: deform bilinear sample + depthwise ----------------
// Warp = 1 pixel, lane owns 4 channels (float4 gathers, fully coalesced 512B).
__global__ void k_deform(const float* __restrict__ wdw, const float* __restrict__ bdw) {
    __shared__ __align__(16) float s_wdw[9 * 128];  // s_wdw[k*128 + c]
    __shared__ int   s_idx[8][36];
    __shared__ float s_wt [8][36];
    const int t    = threadIdx.x;         // 256 threads, 8 warps
    const int wrp  = t >> 5;
    const int lane = t & 31;
    const int pix  = blockIdx.x * 8 + wrp;
    const int b = pix >> 14;
    const int rm = pix & 16383;
    const int h = rm >> 7;
    const int w = rm & 127;

    // transpose depthwise weights into smem: s_wdw[k*128+c] = wdw[c*9+k]
    for (int i = t; i < 9 * 128; i += 256) {
        int c = i & 127, k = i >> 7;
        s_wdw[k * 128 + c] = wdw[c * 9 + k];
    }
    // lanes 0..8 compute the 4 bilinear corners for their tap
    if (lane < 9) {
        const int k = lane;
        const int base = pix * OFFC;
        float dy = g_offmask[base + 2 * k];
        float dx = g_offmask[base + 2 * k + 1];
        float mk = g_offmask[base + 18 + k];
        float py = (float)h + (float)(k / 3 - 1) + dy;
        float px = (float)w + (float)(k % 3 - 1) + dx;
        float y0f = floorf(py), x0f = floorf(px);
        float wy = py - y0f, wx = px - x0f;
        int y0 = (int)y0f, x0 = (int)x0f;
        #pragma unroll
        for (int cor = 0; cor < 4; cor++) {
            int iy = cor >> 1, ix = cor & 1;
            int yc = y0 + iy, xc = x0 + ix;
            float valid = (yc >= 0 && yc < H_ && xc >= 0 && xc < W_) ? 1.f : 0.f;
            int yi = min(max(yc, 0), H_ - 1);
            int xi = min(max(xc, 0), W_ - 1);
            s_idx[wrp][k * 4 + cor] = ((b * H_ + yi) * W_ + xi) * C_;
            s_wt [wrp][k * 4 + cor] = valid * mk * (iy ? wy : 1.f - wy) * (ix ? wx : 1.f - wx);
        }
    }
    __syncthreads();

    float4 acc = ((const float4*)bdw)[lane];
    #pragma unroll
    for (int k = 0; k < 9; k++) {
        float4 v = make_float4(0.f, 0.f, 0.f, 0.f);
        #pragma unroll
        for (int cor = 0; cor < 4; cor++) {
            int   idx = s_idx[wrp][k * 4 + cor];
            float wt  = s_wt [wrp][k * 4 + cor];
            float4 tv = *(const float4*)(g_xnhwc + idx + 4 * lane);
            v.x = fmaf(wt, tv.x, v.x);
            v.y = fmaf(wt, tv.y, v.y);
            v.z = fmaf(wt, tv.z, v.z);
            v.w = fmaf(wt, tv.w, v.w);
        }
        float4 wk = *(const float4*)(s_wdw + k * 128 + 4 * lane);
        acc.x = fmaf(v.x, wk.x, acc.x);
        acc.y = fmaf(v.y, wk.y, acc.y);
        acc.z = fmaf(v.z, wk.z, acc.z);
        acc.w = fmaf(v.w, wk.w, acc.w);
    }
    ((float4*)(g_mid + (size_t)pix * C_))[lane] = acc;
}

// ---------------- kernel 4: pointwise GEMM 128px x 128o, K-chunked 32 ----------------
#define PWP 132

__global__ void __launch_bounds__(256, 2)
k_pointwise(const float* __restrict__ wpw, const float* __restrict__ bpw,
            float* __restrict__ out) {
    __shared__ __align__(16) float sx[32 * PWP];   // sx[c][px]
    __shared__ __align__(16) float sw[32 * PWP];   // sw[c][o]
    const int tid = threadIdx.x;
    const int p0  = blockIdx.x * 128;
    const int ot  = blockIdx.y * 128;
    const int pg  = tid & 15, og = tid >> 4;
    const int px0 = pg * 8, o0 = og * 8;

    float acc[8][8];
    #pragma unroll
    for (int i = 0; i < 8; i++)
        #pragma unroll
        for (int j = 0; j < 8; j++) acc[i][j] = 0.f;

    for (int cc = 0; cc < 4; cc++) {
        #pragma unroll
        for (int l = 0; l < 4; l++) {
            int f  = tid + l * 256;        // 0..1023
            int c4 = f >> 7;               // 0..7
            int px = f & 127;
            float4 v = *(const float4*)(g_mid + (size_t)(p0 + px) * C_ + cc * 32 + c4 * 4);
            sx[(c4 * 4 + 0) * PWP + px] = v.x;
            sx[(c4 * 4 + 1) * PWP + px] = v.y;
            sx[(c4 * 4 + 2) * PWP + px] = v.z;
            sx[(c4 * 4 + 3) * PWP + px] = v.w;
            float4 u = *(const float4*)(wpw + (size_t)(ot + px) * C_ + cc * 32 + c4 * 4);
            sw[(c4 * 4 + 0) * PWP + px] = u.x;
            sw[(c4 * 4 + 1) * PWP + px] = u.y;
            sw[(c4 * 4 + 2) * PWP + px] = u.z;
            sw[(c4 * 4 + 3) * PWP + px] = u.w;
        }
        __syncthreads();

        #pragma unroll
        for (int c = 0; c < 32; c++) {
            float4 xa = *(const float4*)(sx + c * PWP + px0);
            float4 xb = *(const float4*)(sx + c * PWP + px0 + 4);
            float4 wa = *(const float4*)(sw + c * PWP + o0);
            float4 wb = *(const float4*)(sw + c * PWP + o0 + 4);
            float xr[8] = {xa.x, xa.y, xa.z, xa.w, xb.x, xb.y, xb.z, xb.w};
            float wr[8] = {wa.x, wa.y, wa.z, wa.w, wb.x, wb.y, wb.z, wb.w};
            #pragma unroll
            for (int i = 0; i < 8; i++)
                #pragma unroll
                for (int j = 0; j < 8; j++)
                    acc[i][j] = fmaf(wr[i], xr[j], acc[i][j]);
        }
        __syncthreads();
    }

    const int bb  = p0 >> 14;        // pixel tile lies within one batch image
    const int hw0 = p0 & 16383;
    #pragma unroll
    for (int i = 0; i < 8; i++) {
        const int o = ot + o0 + i;
        const float bias = bpw[o];
        float* op = out + ((size_t)bb * O_ + o) * HW_ + hw0 + px0;
        float4 s0 = make_float4(acc[i][0] + bias, acc[i][1] + bias,
                                acc[i][2] + bias, acc[i][3] + bias);
        float4 s1 = make_float4(acc[i][4] + bias, acc[i][5] + bias,
                                acc[i][6] + bias, acc[i][7] + bias);
        *(float4*)(op)     = s0;
        *(float4*)(op + 4) = s1;
    }
}

// ---------------- launch ----------------
extern "C" void kernel_launch(void* const* d_in, const int* in_sizes, int n_in,
                              void* d_out, int out_size) {
    const float* x     = (const float*)d_in[0];
    const float* w_off = (const float*)d_in[1];
    const float* b_off = (const float*)d_in[2];
    const float* w_dw  = (const float*)d_in[3];
    const float* b_dw  = (const float*)d_in[4];
    const float* w_pw  = (const float*)d_in[5];
    const float* b_pw  = (const float*)d_in[6];
    float* out = (float*)d_out;

    cudaFuncSetAttribute(k_offconv, cudaFuncAttributeMaxDynamicSharedMemorySize, OFF_SMEM);

    k_transpose<<<dim3(HW_/32, C_/32, B_), dim3(32, 8)>>>(x);
    k_offconv  <<<dim3(H_/2, B_), 256, OFF_SMEM>>>(w_off, b_off);
    k_deform   <<<NPX/8, 256>>>(w_dw, b_dw);
    k_pointwise<<<dim3(NPX/128, O_/128), 256>>>(w_pw, b_pw, out);
}